// round 5
// baseline (speedup 1.0000x reference)
#include <cuda_runtime.h>
#include <cuda_bf16.h>
#include <cstdint>

#define NDIM 4096
#define NB   32
#define BSZ  128
#define LAT  64
#define NCOL (NB * LAT)   // 2048

// Static device scratch.
__device__ __nv_bfloat16 g_Wb[(size_t)NDIM * NDIM];      // W hi bf16 (GEMM fast path)
__device__ __nv_bfloat16 g_Mt[2][(size_t)NCOL * NDIM];   // Mt[n,k]=M[k,n]; [0]=hi,[1]=lo
__device__ __nv_bfloat16 g_WeT[2][LAT * BSZ];            // WeT[t,c]=We[c,t]; hi/lo
__device__ float g_Y[(size_t)NDIM * NCOL];
__device__ float g_What[(size_t)NDIM * NDIM];            // zero-init; written only where flag set
__device__ unsigned char g_flags[NDIM * NB];

// ---------------------------------------------------------------------------
// Base-target helpers (sm_80+)
// ---------------------------------------------------------------------------
__device__ __forceinline__ uint32_t smem_u32(const void* p) {
    uint32_t a;
    asm("{ .reg .u64 t; cvta.to.shared.u64 t, %1; cvt.u32.u64 %0, t; }" : "=r"(a) : "l"(p));
    return a;
}
#define CP_ASYNC16(s, g) asm volatile("cp.async.cg.shared.global [%0], [%1], 16;" :: "r"(s), "l"(g))
#define CP_COMMIT()      asm volatile("cp.async.commit_group;" ::: "memory")
#define CP_WAIT(n)       asm volatile("cp.async.wait_group %0;" :: "n"(n) : "memory")

__device__ __forceinline__ void ldm_x4(uint32_t addr, uint32_t r[4]) {
    asm volatile("ldmatrix.sync.aligned.m8n8.x4.shared.b16 {%0,%1,%2,%3}, [%4];"
                 : "=r"(r[0]), "=r"(r[1]), "=r"(r[2]), "=r"(r[3]) : "r"(addr));
}
__device__ __forceinline__ void mma_bf16(float* c, const uint32_t a[4], uint32_t b0, uint32_t b1) {
    asm volatile(
        "mma.sync.aligned.m16n8k16.row.col.f32.bf16.bf16.f32 "
        "{%0,%1,%2,%3}, {%4,%5,%6,%7}, {%8,%9}, {%0,%1,%2,%3};"
        : "+f"(c[0]), "+f"(c[1]), "+f"(c[2]), "+f"(c[3])
        : "r"(a[0]), "r"(a[1]), "r"(a[2]), "r"(a[3]), "r"(b0), "r"(b1));
}
__device__ __forceinline__ void split2(float v, __nv_bfloat16& hi, __nv_bfloat16& lo) {
    hi = __float2bfloat16(v);
    lo = __float2bfloat16(v - __bfloat162float(hi));
}

#define RS 80   // smem row stride: 32 bf16 (64B) + 16B pad -> conflict-free ldmatrix

// ---------------------------------------------------------------------------
// Prep kernels
// ---------------------------------------------------------------------------
__global__ void kernCvtW(const float* __restrict__ src) {
    size_t idx = (size_t)blockIdx.x * blockDim.x + threadIdx.x;   // per 8 elems
    const float4* s = reinterpret_cast<const float4*>(src) + idx * 2;
    float4 a = s[0], b = s[1];
    __nv_bfloat162 p0 = __floats2bfloat162_rn(a.x, a.y);
    __nv_bfloat162 p1 = __floats2bfloat162_rn(a.z, a.w);
    __nv_bfloat162 p2 = __floats2bfloat162_rn(b.x, b.y);
    __nv_bfloat162 p3 = __floats2bfloat162_rn(b.z, b.w);
    uint4 v;
    v.x = *reinterpret_cast<uint32_t*>(&p0);
    v.y = *reinterpret_cast<uint32_t*>(&p1);
    v.z = *reinterpret_cast<uint32_t*>(&p2);
    v.w = *reinterpret_cast<uint32_t*>(&p3);
    *reinterpret_cast<uint4*>(g_Wb + idx * 8) = v;
}

__global__ void kernWeT(const float* __restrict__ We) {
    int idx = blockIdx.x * blockDim.x + threadIdx.x;   // 8192
    int t = idx >> 7, c = idx & 127;
    __nv_bfloat16 h, l;
    split2(We[c * LAT + t], h, l);
    g_WeT[0][idx] = h;
    g_WeT[1][idx] = l;
}

__global__ void kernFillMt(const float* __restrict__ We) {
    int idx = blockIdx.x * blockDim.x + threadIdx.x;   // NCOL*512
    int n = idx >> 9, g = idx & 511, k0 = g * 8;
    int j = n >> 6, t = n & 63, s = j * BSZ;
    __nv_bfloat16 h[8], l[8];
    if (k0 >= s && k0 < s + BSZ) {
#pragma unroll
        for (int q = 0; q < 8; ++q) split2(We[(k0 + q - s) * LAT + t], h[q], l[q]);
    } else {
#pragma unroll
        for (int q = 0; q < 8; ++q) { h[q] = __float2bfloat16(0.f); l[q] = h[q]; }
    }
    *reinterpret_cast<uint4*>(g_Mt[0] + (size_t)n * NDIM + k0) = *reinterpret_cast<uint4*>(h);
    *reinterpret_cast<uint4*>(g_Mt[1] + (size_t)n * NDIM + k0) = *reinterpret_cast<uint4*>(l);
}

// ---------------------------------------------------------------------------
// kernG: Mt G-blocks.  C[t(64), kr(128)] = sum_c WeT[t,c] * L[k0+kr, s+c].
// Split-precision HMMA (fp32-accurate output). L read as fp32, split in-reg.
// Grid (32 kt, 32 j), active iff kt > j. 128 threads.
// smem: A(hi,lo) 2x5120 + B(hi,lo) 2x10240 = 30720 B.
// ---------------------------------------------------------------------------
__global__ void __launch_bounds__(128, 4) kernG(const float* __restrict__ L) {
    int kt = blockIdx.x, j = blockIdx.y;
    if (kt <= j) return;
    extern __shared__ __align__(128) char sm[];
    uint32_t sb = smem_u32(sm);
    uint32_t sA[2] = {sb, sb + 5120};
    uint32_t sB[2] = {sb + 10240, sb + 20480};
    int tid = threadIdx.x, wid = tid >> 5, lane = tid & 31;
    int k0g = kt * BSZ, s = j * BSZ;
    int wm = (wid & 1) * 32, wn = (wid >> 1) * 64;

    float acc[2][8][4];
#pragma unroll
    for (int i = 0; i < 2; ++i)
#pragma unroll
        for (int q = 0; q < 8; ++q)
#pragma unroll
            for (int z = 0; z < 4; ++z) acc[i][q][z] = 0.f;

    for (int it = 0; it < 4; ++it) {            // K=128, BK=32
        int kk = it * 32;
        // A (WeT hi/lo) via cp.async: 64 rows x 4ch x 2prec = 512 chunks
#pragma unroll
        for (int q = 0; q < 4; ++q) {
            int id = tid + q * 128;
            int prec = id >> 8, rem = id & 255, row = rem >> 2, ch = rem & 3;
            CP_ASYNC16(sA[prec] + row * RS + ch * 16,
                       g_WeT[prec] + row * BSZ + kk + ch * 8);
        }
        CP_COMMIT();
        // B (L fp32 -> split in-register): 128 rows x 8 float4 = 1024
#pragma unroll
        for (int q = 0; q < 8; ++q) {
            int id = tid + q * 128;
            int row = id >> 3, c = (id & 7) * 4;
            float4 v = *reinterpret_cast<const float4*>(
                L + (size_t)(k0g + row) * NDIM + s + kk + c);
            __nv_bfloat16 h0, l0, h1, l1, h2, l2, h3, l3;
            split2(v.x, h0, l0); split2(v.y, h1, l1);
            split2(v.z, h2, l2); split2(v.w, h3, l3);
            __nv_bfloat162 hA(h0, h1), hB(h2, h3), lA(l0, l1), lB(l2, l3);
            uint2 uh, ul;
            uh.x = *reinterpret_cast<uint32_t*>(&hA); uh.y = *reinterpret_cast<uint32_t*>(&hB);
            ul.x = *reinterpret_cast<uint32_t*>(&lA); ul.y = *reinterpret_cast<uint32_t*>(&lB);
            *reinterpret_cast<uint2*>(sm + 10240 + row * RS + c * 2) = uh;
            *reinterpret_cast<uint2*>(sm + 20480 + row * RS + c * 2) = ul;
        }
        CP_WAIT(0);
        __syncthreads();

#pragma unroll
        for (int ks = 0; ks < 2; ++ks) {
            uint32_t ah[2][4], al[2][4];
#pragma unroll
            for (int mf = 0; mf < 2; ++mf) {
                uint32_t ao = (wm + mf * 16 + (lane & 15)) * RS + ks * 32 + (lane >> 4) * 16;
                ldm_x4(sA[0] + ao, ah[mf]);
                ldm_x4(sA[1] + ao, al[mf]);
            }
            uint32_t bh[8][2];
#pragma unroll
            for (int p = 0; p < 4; ++p) {
                uint32_t r[4];
                int g = lane >> 3;
                int row = wn + p * 16 + ((g >> 1) << 3) + (lane & 7);
                ldm_x4(sB[0] + row * RS + ks * 32 + (g & 1) * 16, r);
                bh[p * 2][0] = r[0]; bh[p * 2][1] = r[1];
                bh[p * 2 + 1][0] = r[2]; bh[p * 2 + 1][1] = r[3];
            }
#pragma unroll
            for (int mf = 0; mf < 2; ++mf)
#pragma unroll
                for (int nf = 0; nf < 8; ++nf) {
                    mma_bf16(acc[mf][nf], ah[mf], bh[nf][0], bh[nf][1]);
                    mma_bf16(acc[mf][nf], al[mf], bh[nf][0], bh[nf][1]);
                }
            uint32_t bl[8][2];
#pragma unroll
            for (int p = 0; p < 4; ++p) {
                uint32_t r[4];
                int g = lane >> 3;
                int row = wn + p * 16 + ((g >> 1) << 3) + (lane & 7);
                ldm_x4(sB[1] + row * RS + ks * 32 + (g & 1) * 16, r);
                bl[p * 2][0] = r[0]; bl[p * 2][1] = r[1];
                bl[p * 2 + 1][0] = r[2]; bl[p * 2 + 1][1] = r[3];
            }
#pragma unroll
            for (int mf = 0; mf < 2; ++mf)
#pragma unroll
                for (int nf = 0; nf < 8; ++nf)
                    mma_bf16(acc[mf][nf], ah[mf], bl[nf][0], bl[nf][1]);
        }
        __syncthreads();
    }

    int jn = j * LAT;
#pragma unroll
    for (int mf = 0; mf < 2; ++mf) {
        int t0 = wm + mf * 16 + (lane >> 2);
#pragma unroll
        for (int nf = 0; nf < 8; ++nf) {
            int kr = wn + nf * 8 + 2 * (lane & 3);
            __nv_bfloat16 h0, l0, h1, l1, h2, l2, h3, l3;
            split2(acc[mf][nf][0], h0, l0);
            split2(acc[mf][nf][1], h1, l1);
            split2(acc[mf][nf][2], h2, l2);
            split2(acc[mf][nf][3], h3, l3);
            size_t o0 = (size_t)(jn + t0) * NDIM + k0g + kr;
            size_t o1 = (size_t)(jn + t0 + 8) * NDIM + k0g + kr;
            *reinterpret_cast<__nv_bfloat162*>(g_Mt[0] + o0) = __nv_bfloat162(h0, h1);
            *reinterpret_cast<__nv_bfloat162*>(g_Mt[1] + o0) = __nv_bfloat162(l0, l1);
            *reinterpret_cast<__nv_bfloat162*>(g_Mt[0] + o1) = __nv_bfloat162(h2, h3);
            *reinterpret_cast<__nv_bfloat162*>(g_Mt[1] + o1) = __nv_bfloat162(l2, l3);
        }
    }
}

// ---------------------------------------------------------------------------
// kernGemmY: Y[4096,2048] = W @ M^T, plain bf16 HMMA (hi x hi), fp32 accum.
// BM=128 BN=128 BK=32, 256 thr (8 warps 2x4, warp 64x32). Double-buffered
// cp.async (2 stages x 20480 B = 40960). k starts at n0*2 (triangular M).
// Precision guarded by the boundary-recompute in kernSteps.
// ---------------------------------------------------------------------------
__global__ void __launch_bounds__(256, 2) kernGemmY() {
    extern __shared__ __align__(128) char sm[];
    const int TSZ = 128 * RS;                 // 10240
    const int STG = 2 * TSZ;                  // 20480 per stage (A + B)
    uint32_t sb = smem_u32(sm);
    int tid = threadIdx.x, wid = tid >> 5, lane = tid & 31;
    int m0 = blockIdx.x * 128, n0 = blockIdx.y * 128;
    int kst = n0 * 2;
    int niter = (NDIM - kst) / 32;
    int wm = (wid & 1) * 64, wn = (wid >> 1) * 32;

    float acc[4][4][4];
#pragma unroll
    for (int i = 0; i < 4; ++i)
#pragma unroll
        for (int q = 0; q < 4; ++q)
#pragma unroll
            for (int z = 0; z < 4; ++z) acc[i][q][z] = 0.f;

    // prologue: stage 0
    {
        uint32_t s_a = sb, s_b = sb + TSZ;
#pragma unroll
        for (int q = 0; q < 2; ++q) {
            int id = tid + q * 256, row = id >> 2, ch = id & 3;
            CP_ASYNC16(s_a + row * RS + ch * 16, g_Wb + (size_t)(m0 + row) * NDIM + kst + ch * 8);
            CP_ASYNC16(s_b + row * RS + ch * 16, g_Mt[0] + (size_t)(n0 + row) * NDIM + kst + ch * 8);
        }
        CP_COMMIT();
    }

    for (int it = 0; it < niter; ++it) {
        if (it + 1 < niter) {
            int k0 = kst + (it + 1) * 32;
            uint32_t s_a = sb + ((it + 1) & 1) * STG, s_b = s_a + TSZ;
#pragma unroll
            for (int q = 0; q < 2; ++q) {
                int id = tid + q * 256, row = id >> 2, ch = id & 3;
                CP_ASYNC16(s_a + row * RS + ch * 16, g_Wb + (size_t)(m0 + row) * NDIM + k0 + ch * 8);
                CP_ASYNC16(s_b + row * RS + ch * 16, g_Mt[0] + (size_t)(n0 + row) * NDIM + k0 + ch * 8);
            }
            CP_COMMIT();
            CP_WAIT(1);
        } else {
            CP_WAIT(0);
        }
        __syncthreads();
        uint32_t s_a = sb + (it & 1) * STG, s_b = s_a + TSZ;
#pragma unroll
        for (int ks = 0; ks < 2; ++ks) {
            uint32_t a[4][4];
#pragma unroll
            for (int mf = 0; mf < 4; ++mf)
                ldm_x4(s_a + (wm + mf * 16 + (lane & 15)) * RS + ks * 32 + (lane >> 4) * 16, a[mf]);
            uint32_t b[4][2];
#pragma unroll
            for (int p = 0; p < 2; ++p) {
                uint32_t r[4];
                int g = lane >> 3;
                int row = wn + p * 16 + ((g >> 1) << 3) + (lane & 7);
                ldm_x4(s_b + row * RS + ks * 32 + (g & 1) * 16, r);
                b[p * 2][0] = r[0]; b[p * 2][1] = r[1];
                b[p * 2 + 1][0] = r[2]; b[p * 2 + 1][1] = r[3];
            }
#pragma unroll
            for (int mf = 0; mf < 4; ++mf)
#pragma unroll
                for (int nf = 0; nf < 4; ++nf)
                    mma_bf16(acc[mf][nf], a[mf], b[nf][0], b[nf][1]);
        }
        __syncthreads();
    }

#pragma unroll
    for (int mf = 0; mf < 4; ++mf) {
        int row = m0 + wm + mf * 16 + (lane >> 2);
#pragma unroll
        for (int nf = 0; nf < 4; ++nf) {
            int col = n0 + wn + nf * 8 + 2 * (lane & 3);
            *reinterpret_cast<float2*>(g_Y + (size_t)row * NCOL + col) =
                make_float2(acc[mf][nf][0], acc[mf][nf][1]);
            *reinterpret_cast<float2*>(g_Y + (size_t)(row + 8) * NCOL + col) =
                make_float2(acc[mf][nf][2], acc[mf][nf][3]);
        }
    }
}

// ---------------------------------------------------------------------------
// kernSteps: 32 fused sequential quantization steps + boundary-exact recompute.
// If |y - rint(y)| is within 0.08 of 0.5 (bf16 GEMM can't guarantee the side),
// recompute that element's Y exactly in fp32 from weight and Mt(hi+lo).
// ---------------------------------------------------------------------------
__global__ void kernSteps(const float* __restrict__ rn, const float* __restrict__ Wd,
                          const float* __restrict__ W) {
    int rloc = threadIdx.x >> 6, t = threadIdx.x & 63;
    int r = blockIdx.x * 4 + rloc;

    __shared__ float s_yh[4][64];
    __shared__ int s_nz[4];
    __shared__ unsigned char fl[4][32];

    float rnv = rn[r];
    if (t < 32) fl[rloc][t] = 0;

    for (int jb = NB - 1; jb >= 0; --jb) {
        __syncthreads();
        if (t == 0) s_nz[rloc] = 0;
        __syncthreads();

        float y0 = g_Y[(size_t)r * NCOL + jb * LAT + t];
        float fb = 0.f;
        for (int jj = jb + 1; jj < NB; ++jj) {
            if (fl[rloc][jj]) {
                const float* wh = g_What + (size_t)r * NDIM + jj * BSZ;
                size_t go = (size_t)(jb * LAT + t) * NDIM + jj * BSZ;
#pragma unroll 4
                for (int k = 0; k < BSZ; ++k) {
                    float gv = __bfloat162float(g_Mt[0][go + k]) +
                               __bfloat162float(g_Mt[1][go + k]);
                    fb = fmaf(wh[k], gv, fb);
                }
            }
        }
        float y = (y0 - fb) / rnv;
        // Boundary guard: bf16 GEMM error < ~3e-3 on y; recompute exactly if
        // within 0.08 of a rounding boundary (expected: never taken).
        if (fabsf(fabsf(y - rintf(y)) - 0.5f) < 0.08f) {
            float ex = 0.f;
            int s = jb * BSZ;
            const float* wr = W + (size_t)r * NDIM;
            size_t mo = (size_t)(jb * LAT + t) * NDIM;
            for (int k = s; k < NDIM; ++k) {
                float mv = __bfloat162float(g_Mt[0][mo + k]) +
                           __bfloat162float(g_Mt[1][mo + k]);
                ex = fmaf(wr[k], mv, ex);
            }
            y = (ex - fb) / rnv;
        }
        float yh = rintf(y);
        s_yh[rloc][t] = yh;
        if (yh != 0.f) s_nz[rloc] = 1;
        __syncthreads();

        int nz = s_nz[rloc];
        if (nz) {
            float x0 = 0.f, x1 = 0.f;
#pragma unroll 8
            for (int tt = 0; tt < 64; ++tt) {
                float v = s_yh[rloc][tt];
                x0 = fmaf(v, Wd[tt * BSZ + t], x0);
                x1 = fmaf(v, Wd[tt * BSZ + t + 64], x1);
            }
            float* dst = g_What + (size_t)r * NDIM + jb * BSZ;
            dst[t] = x0;
            dst[t + 64] = x1;
        }
        if (t == 0) {
            fl[rloc][jb] = (unsigned char)nz;
            g_flags[r * NB + jb] = (unsigned char)nz;
        }
    }
}

// ---------------------------------------------------------------------------
// kernOut: out = bias + x @ (W_hat * rn)^T, skipping exactly-zero k-blocks.
// ---------------------------------------------------------------------------
__global__ void kernOut(const float* __restrict__ x, const float* __restrict__ rn,
                        const float* __restrict__ bias, float* __restrict__ out) {
    __shared__ __align__(16) float xs[16][64];
    __shared__ __align__(16) float ws[16][64];
    __shared__ unsigned char shf[NB];

    int b0 = blockIdx.x * 64;
    int m0 = blockIdx.y * 64;
    int tid = threadIdx.x;

    if (tid < NB) {
        unsigned char f = 0;
        for (int mm = 0; mm < 64; ++mm) f |= g_flags[(m0 + mm) * NB + tid];
        shf[tid] = f;
    }
    __syncthreads();

    int tr = tid >> 4, tc = tid & 15;
    int l_r = tid >> 2, l_q = (tid & 3) * 4;

    float acc[4][4];
#pragma unroll
    for (int i = 0; i < 4; ++i)
#pragma unroll
        for (int q = 0; q < 4; ++q) acc[i][q] = 0.f;

    float rnm = rn[m0 + l_r];

    for (int jj = 0; jj < NB; ++jj) {
        if (!shf[jj]) continue;
        for (int k0 = 0; k0 < BSZ; k0 += 16) {
            float4 xv = *reinterpret_cast<const float4*>(x + (size_t)(b0 + l_r) * NDIM + jj * BSZ + k0 + l_q);
            xs[l_q + 0][l_r] = xv.x; xs[l_q + 1][l_r] = xv.y;
            xs[l_q + 2][l_r] = xv.z; xs[l_q + 3][l_r] = xv.w;
            float4 wv = *reinterpret_cast<const float4*>(g_What + (size_t)(m0 + l_r) * NDIM + jj * BSZ + k0 + l_q);
            ws[l_q + 0][l_r] = wv.x * rnm; ws[l_q + 1][l_r] = wv.y * rnm;
            ws[l_q + 2][l_r] = wv.z * rnm; ws[l_q + 3][l_r] = wv.w * rnm;
            __syncthreads();
#pragma unroll
            for (int kk = 0; kk < 16; ++kk) {
                float4 a4 = *reinterpret_cast<const float4*>(&xs[kk][tr * 4]);
                float4 b4 = *reinterpret_cast<const float4*>(&ws[kk][tc * 4]);
                float a[4] = {a4.x, a4.y, a4.z, a4.w};
                float b[4] = {b4.x, b4.y, b4.z, b4.w};
#pragma unroll
                for (int i = 0; i < 4; ++i)
#pragma unroll
                    for (int q = 0; q < 4; ++q)
                        acc[i][q] = fmaf(a[i], b[q], acc[i][q]);
            }
            __syncthreads();
        }
    }

#pragma unroll
    for (int i = 0; i < 4; ++i) {
        int b = b0 + tr * 4 + i;
#pragma unroll
        for (int q = 0; q < 4; ++q) {
            int m = m0 + tc * 4 + q;
            out[(size_t)b * NDIM + m] = bias[m] + acc[i][q];
        }
    }
}

// ---------------------------------------------------------------------------
// kernel_launch: inputs (metadata order): x, weight, bias, row_norm, L, We, Wd
// ---------------------------------------------------------------------------
extern "C" void kernel_launch(void* const* d_in, const int* in_sizes, int n_in,
                              void* d_out, int out_size) {
    (void)in_sizes; (void)n_in; (void)out_size;
    const float* x      = (const float*)d_in[0];
    const float* weight = (const float*)d_in[1];
    const float* bias   = (const float*)d_in[2];
    const float* rn     = (const float*)d_in[3];
    const float* L      = (const float*)d_in[4];
    const float* We     = (const float*)d_in[5];
    const float* Wd     = (const float*)d_in[6];
    float* out          = (float*)d_out;

    kernCvtW<<<8192, 256>>>(weight);                      // W -> bf16 hi
    kernWeT<<<32, 256>>>(We);                             // We^T split
    kernFillMt<<<4096, 256>>>(We);                        // Mt diag blocks split + zeros
    kernG<<<dim3(32, 32), 128, 30720>>>(L);               // Mt G-blocks, split HMMA (L fp32 direct)
    kernGemmY<<<dim3(32, 16), 256, 40960>>>();            // Y = W @ M, bf16 HMMA (guarded)
    kernSteps<<<1024, 256>>>(rn, Wd, weight);             // fused steps + boundary recompute
    kernOut<<<dim3(64, 64), 256>>>(x, rn, bias, out);     // output GEMM, zero-block skip
}

// round 6
// speedup vs baseline: 2.0843x; 2.0843x over previous
#include <cuda_runtime.h>
#include <cuda_bf16.h>
#include <cstdint>

#define NDIM 4096
#define NB   32
#define BSZ  128
#define LAT  64
#define NCOL (NB * LAT)   // 2048

// Static device scratch; [0]=hi, [1]=lo (value = hi+lo bf16 split).
__device__ __nv_bfloat16 g_Wb[2][(size_t)NDIM * NDIM];
__device__ __nv_bfloat16 g_Mt[2][(size_t)NCOL * NDIM];   // Mt[n,k] = M[k,n]
__device__ __nv_bfloat16 g_WeT[2][LAT * BSZ];            // WeT[t,c] = We[c,t]
__device__ float g_Y[(size_t)NDIM * NCOL];
__device__ float g_What[(size_t)NDIM * NDIM];            // zero-init; written only where flag set
__device__ unsigned char g_flags[NDIM * NB];

// ---------------------------------------------------------------------------
// Base-target helpers (sm_80+)
// ---------------------------------------------------------------------------
__device__ __forceinline__ uint32_t smem_u32(const void* p) {
    uint32_t a;
    asm("{ .reg .u64 t; cvta.to.shared.u64 t, %1; cvt.u32.u64 %0, t; }" : "=r"(a) : "l"(p));
    return a;
}
#define CP_ASYNC16(s, g) asm volatile("cp.async.cg.shared.global [%0], [%1], 16;" :: "r"(s), "l"(g))
#define CP_COMMIT()      asm volatile("cp.async.commit_group;" ::: "memory")
#define CP_WAIT(n)       asm volatile("cp.async.wait_group %0;" :: "n"(n) : "memory")

__device__ __forceinline__ void ldm_x4(uint32_t addr, uint32_t r[4]) {
    asm volatile("ldmatrix.sync.aligned.m8n8.x4.shared.b16 {%0,%1,%2,%3}, [%4];"
                 : "=r"(r[0]), "=r"(r[1]), "=r"(r[2]), "=r"(r[3]) : "r"(addr));
}
__device__ __forceinline__ void mma_bf16(float* c, const uint32_t a[4], uint32_t b0, uint32_t b1) {
    asm volatile(
        "mma.sync.aligned.m16n8k16.row.col.f32.bf16.bf16.f32 "
        "{%0,%1,%2,%3}, {%4,%5,%6,%7}, {%8,%9}, {%0,%1,%2,%3};"
        : "+f"(c[0]), "+f"(c[1]), "+f"(c[2]), "+f"(c[3])
        : "r"(a[0]), "r"(a[1]), "r"(a[2]), "r"(a[3]), "r"(b0), "r"(b1));
}
__device__ __forceinline__ void split2(float v, __nv_bfloat16& hi, __nv_bfloat16& lo) {
    hi = __float2bfloat16(v);
    lo = __float2bfloat16(v - __bfloat162float(hi));
}

#define RS 80   // smem row stride: 32 bf16 (64B) + 16B pad -> conflict-free ldmatrix

// ---------------------------------------------------------------------------
// kernCvtW: W fp32 -> (hi, lo) bf16 split.                       [launch 0]
// ---------------------------------------------------------------------------
__global__ void kernCvtW(const float* __restrict__ src) {
    size_t idx = (size_t)blockIdx.x * blockDim.x + threadIdx.x;   // per 8 elems
    const float4* s = reinterpret_cast<const float4*>(src) + idx * 2;
    float4 a = s[0], b = s[1];
    float v[8] = {a.x, a.y, a.z, a.w, b.x, b.y, b.z, b.w};
    __nv_bfloat16 h[8], l[8];
#pragma unroll
    for (int q = 0; q < 8; ++q) split2(v[q], h[q], l[q]);
    *reinterpret_cast<uint4*>(g_Wb[0] + idx * 8) = *reinterpret_cast<uint4*>(h);
    *reinterpret_cast<uint4*>(g_Wb[1] + idx * 8) = *reinterpret_cast<uint4*>(l);
}

// ---------------------------------------------------------------------------
// kernWeT: We^T split.                                            [launch 1]
// ---------------------------------------------------------------------------
__global__ void kernWeT(const float* __restrict__ We) {
    int idx = blockIdx.x * blockDim.x + threadIdx.x;   // 8192
    int t = idx >> 7, c = idx & 127;
    __nv_bfloat16 h, l;
    split2(We[c * LAT + t], h, l);
    g_WeT[0][idx] = h;
    g_WeT[1][idx] = l;
}

// ---------------------------------------------------------------------------
// kernG: builds the FULL Mt.                                      [launch 2]
//   kt > j : G block via split-precision HMMA (L read fp32, split in-reg)
//   kt == j: diagonal We block (split)
//   kt < j : zero fill
// Grid (32 kt, 32 j), 128 threads. smem 30720 B (MMA path only).
// ---------------------------------------------------------------------------
__global__ void __launch_bounds__(128, 4) kernG(const float* __restrict__ L,
                                                const float* __restrict__ We) {
    int kt = blockIdx.x, j = blockIdx.y;
    int tid = threadIdx.x;
    int jn = j * LAT, s = j * BSZ;

    if (kt < j) {        // zero region: 64 rows x 128 cols
        uint4 z = make_uint4(0, 0, 0, 0);
        for (int i = tid; i < 64 * 16; i += 128) {
            int rr = i >> 4, c = i & 15;
            size_t o = (size_t)(jn + rr) * NDIM + kt * BSZ + c * 8;
            *reinterpret_cast<uint4*>(g_Mt[0] + o) = z;
            *reinterpret_cast<uint4*>(g_Mt[1] + o) = z;
        }
        return;
    }
    if (kt == j) {       // diagonal: Mt[jn+n][s+tid] = We[tid][n]
        for (int n = 0; n < LAT; ++n) {
            __nv_bfloat16 h, l;
            split2(We[tid * LAT + n], h, l);
            size_t o = (size_t)(jn + n) * NDIM + s + tid;
            g_Mt[0][o] = h;
            g_Mt[1][o] = l;
        }
        return;
    }

    // MMA path (kt > j)
    extern __shared__ __align__(128) char sm[];
    uint32_t sb = smem_u32(sm);
    uint32_t sA[2] = {sb, sb + 5120};
    uint32_t sB[2] = {sb + 10240, sb + 20480};
    int wid = tid >> 5, lane = tid & 31;
    int k0g = kt * BSZ;
    int wm = (wid & 1) * 32, wn = (wid >> 1) * 64;

    float acc[2][8][4];
#pragma unroll
    for (int i = 0; i < 2; ++i)
#pragma unroll
        for (int q = 0; q < 8; ++q)
#pragma unroll
            for (int z = 0; z < 4; ++z) acc[i][q][z] = 0.f;

    for (int it = 0; it < 4; ++it) {            // K=128, BK=32
        int kk = it * 32;
#pragma unroll
        for (int q = 0; q < 4; ++q) {           // A (WeT hi/lo) via cp.async
            int id = tid + q * 128;
            int prec = id >> 8, rem = id & 255, row = rem >> 2, ch = rem & 3;
            CP_ASYNC16(sA[prec] + row * RS + ch * 16,
                       g_WeT[prec] + row * BSZ + kk + ch * 8);
        }
        CP_COMMIT();
#pragma unroll
        for (int q = 0; q < 8; ++q) {           // B: L fp32 -> split in-reg
            int id = tid + q * 128;
            int row = id >> 3, c = (id & 7) * 4;
            float4 v = *reinterpret_cast<const float4*>(
                L + (size_t)(k0g + row) * NDIM + s + kk + c);
            __nv_bfloat16 h0, l0, h1, l1, h2, l2, h3, l3;
            split2(v.x, h0, l0); split2(v.y, h1, l1);
            split2(v.z, h2, l2); split2(v.w, h3, l3);
            __nv_bfloat162 hA(h0, h1), hB(h2, h3), lA(l0, l1), lB(l2, l3);
            uint2 uh, ul;
            uh.x = *reinterpret_cast<uint32_t*>(&hA); uh.y = *reinterpret_cast<uint32_t*>(&hB);
            ul.x = *reinterpret_cast<uint32_t*>(&lA); ul.y = *reinterpret_cast<uint32_t*>(&lB);
            *reinterpret_cast<uint2*>(sm + 10240 + row * RS + c * 2) = uh;
            *reinterpret_cast<uint2*>(sm + 20480 + row * RS + c * 2) = ul;
        }
        CP_WAIT(0);
        __syncthreads();

#pragma unroll
        for (int ks = 0; ks < 2; ++ks) {
            uint32_t ah[2][4];
#pragma unroll
            for (int mf = 0; mf < 2; ++mf)
                ldm_x4(sA[0] + (wm + mf * 16 + (lane & 15)) * RS + ks * 32 + (lane >> 4) * 16, ah[mf]);
            uint32_t bh[8][2];
#pragma unroll
            for (int p = 0; p < 4; ++p) {
                uint32_t r[4];
                int g = lane >> 3;
                int row = wn + p * 16 + ((g >> 1) << 3) + (lane & 7);
                ldm_x4(sB[0] + row * RS + ks * 32 + (g & 1) * 16, r);
                bh[p * 2][0] = r[0]; bh[p * 2][1] = r[1];
                bh[p * 2 + 1][0] = r[2]; bh[p * 2 + 1][1] = r[3];
            }
#pragma unroll
            for (int mf = 0; mf < 2; ++mf)
#pragma unroll
                for (int nf = 0; nf < 8; ++nf)
                    mma_bf16(acc[mf][nf], ah[mf], bh[nf][0], bh[nf][1]);
            uint32_t al[2][4];
#pragma unroll
            for (int mf = 0; mf < 2; ++mf)
                ldm_x4(sA[1] + (wm + mf * 16 + (lane & 15)) * RS + ks * 32 + (lane >> 4) * 16, al[mf]);
#pragma unroll
            for (int mf = 0; mf < 2; ++mf)
#pragma unroll
                for (int nf = 0; nf < 8; ++nf)
                    mma_bf16(acc[mf][nf], al[mf], bh[nf][0], bh[nf][1]);
            uint32_t bl[8][2];
#pragma unroll
            for (int p = 0; p < 4; ++p) {
                uint32_t r[4];
                int g = lane >> 3;
                int row = wn + p * 16 + ((g >> 1) << 3) + (lane & 7);
                ldm_x4(sB[1] + row * RS + ks * 32 + (g & 1) * 16, r);
                bl[p * 2][0] = r[0]; bl[p * 2][1] = r[1];
                bl[p * 2 + 1][0] = r[2]; bl[p * 2 + 1][1] = r[3];
            }
#pragma unroll
            for (int mf = 0; mf < 2; ++mf)
#pragma unroll
                for (int nf = 0; nf < 8; ++nf)
                    mma_bf16(acc[mf][nf], ah[mf], bl[nf][0], bl[nf][1]);
        }
        __syncthreads();
    }

#pragma unroll
    for (int mf = 0; mf < 2; ++mf) {
        int t0 = wm + mf * 16 + (lane >> 2);
#pragma unroll
        for (int nf = 0; nf < 8; ++nf) {
            int kr = wn + nf * 8 + 2 * (lane & 3);
            __nv_bfloat16 h0, l0, h1, l1, h2, l2, h3, l3;
            split2(acc[mf][nf][0], h0, l0);
            split2(acc[mf][nf][1], h1, l1);
            split2(acc[mf][nf][2], h2, l2);
            split2(acc[mf][nf][3], h3, l3);
            size_t o0 = (size_t)(jn + t0) * NDIM + k0g + kr;
            size_t o1 = (size_t)(jn + t0 + 8) * NDIM + k0g + kr;
            *reinterpret_cast<__nv_bfloat162*>(g_Mt[0] + o0) = __nv_bfloat162(h0, h1);
            *reinterpret_cast<__nv_bfloat162*>(g_Mt[1] + o0) = __nv_bfloat162(l0, l1);
            *reinterpret_cast<__nv_bfloat162*>(g_Mt[0] + o1) = __nv_bfloat162(h2, h3);
            *reinterpret_cast<__nv_bfloat162*>(g_Mt[1] + o1) = __nv_bfloat162(l2, l3);
        }
    }
}

// ---------------------------------------------------------------------------
// kernGemmY: Y = W @ M^T, 3-term split HMMA (hh + lh + hl).       [launch 3]
// BM=128 BN=128 BK=32, 256 thr (8 warps 2x4, warp 64x32). Single-stage smem
// 40960 B, 2 CTAs/SM. Fragment loads interleaved with MMAs to keep live regs
// under the 128-reg cap (no spills). k starts at n0*2 (triangular M).
// ---------------------------------------------------------------------------
__global__ void __launch_bounds__(256, 2) kernGemmY() {
    extern __shared__ __align__(128) char sm[];
    const int TSZ = 128 * RS;                 // 10240
    uint32_t sb = smem_u32(sm);
    uint32_t sA[2] = {sb, sb + TSZ};
    uint32_t sB[2] = {sb + 2 * TSZ, sb + 3 * TSZ};
    int tid = threadIdx.x, wid = tid >> 5, lane = tid & 31;
    int m0 = blockIdx.x * 128, n0 = blockIdx.y * 128;
    int kst = n0 * 2;
    int niter = (NDIM - kst) / 32;
    int wm = (wid & 1) * 64, wn = (wid >> 1) * 32;

    float acc[4][4][4];
#pragma unroll
    for (int i = 0; i < 4; ++i)
#pragma unroll
        for (int q = 0; q < 4; ++q)
#pragma unroll
            for (int z = 0; z < 4; ++z) acc[i][q][z] = 0.f;

    for (int it = 0; it < niter; ++it) {
        int k0 = kst + it * 32;
#pragma unroll
        for (int q = 0; q < 4; ++q) {          // A,B hi+lo: 1024 chunks each
            int id = tid + q * 256;
            int prec = id >> 9, rem = id & 511, row = rem >> 2, ch = rem & 3;
            CP_ASYNC16(sA[prec] + row * RS + ch * 16,
                       g_Wb[prec] + (size_t)(m0 + row) * NDIM + k0 + ch * 8);
            CP_ASYNC16(sB[prec] + row * RS + ch * 16,
                       g_Mt[prec] + (size_t)(n0 + row) * NDIM + k0 + ch * 8);
        }
        CP_COMMIT();
        CP_WAIT(0);
        __syncthreads();

#pragma unroll
        for (int ks = 0; ks < 2; ++ks) {
            // hi A fragments (live through the whole ks step)
            uint32_t ah[4][4];
#pragma unroll
            for (int mf = 0; mf < 4; ++mf)
                ldm_x4(sA[0] + (wm + mf * 16 + (lane & 15)) * RS + ks * 32 + (lane >> 4) * 16, ah[mf]);
            // hi B fragments, then hh MMAs
            uint32_t bh[4][2];
#pragma unroll
            for (int p = 0; p < 2; ++p) {
                uint32_t r[4];
                int g = lane >> 3;
                int row = wn + p * 16 + ((g >> 1) << 3) + (lane & 7);
                ldm_x4(sB[0] + row * RS + ks * 32 + (g & 1) * 16, r);
                bh[p * 2][0] = r[0]; bh[p * 2][1] = r[1];
                bh[p * 2 + 1][0] = r[2]; bh[p * 2 + 1][1] = r[3];
            }
#pragma unroll
            for (int mf = 0; mf < 4; ++mf)
#pragma unroll
                for (int nf = 0; nf < 4; ++nf)
                    mma_bf16(acc[mf][nf], ah[mf], bh[nf][0], bh[nf][1]);
            // lo A fragments, lh MMAs (al dies right after)
            uint32_t al[4][4];
#pragma unroll
            for (int mf = 0; mf < 4; ++mf)
                ldm_x4(sA[1] + (wm + mf * 16 + (lane & 15)) * RS + ks * 32 + (lane >> 4) * 16, al[mf]);
#pragma unroll
            for (int mf = 0; mf < 4; ++mf)
#pragma unroll
                for (int nf = 0; nf < 4; ++nf)
                    mma_bf16(acc[mf][nf], al[mf], bh[nf][0], bh[nf][1]);
            // lo B fragments, hl MMAs
            uint32_t bl[4][2];
#pragma unroll
            for (int p = 0; p < 2; ++p) {
                uint32_t r[4];
                int g = lane >> 3;
                int row = wn + p * 16 + ((g >> 1) << 3) + (lane & 7);
                ldm_x4(sB[1] + row * RS + ks * 32 + (g & 1) * 16, r);
                bl[p * 2][0] = r[0]; bl[p * 2][1] = r[1];
                bl[p * 2 + 1][0] = r[2]; bl[p * 2 + 1][1] = r[3];
            }
#pragma unroll
            for (int mf = 0; mf < 4; ++mf)
#pragma unroll
                for (int nf = 0; nf < 4; ++nf)
                    mma_bf16(acc[mf][nf], ah[mf], bl[nf][0], bl[nf][1]);
        }
        __syncthreads();
    }

#pragma unroll
    for (int mf = 0; mf < 4; ++mf) {
        int row = m0 + wm + mf * 16 + (lane >> 2);
#pragma unroll
        for (int nf = 0; nf < 4; ++nf) {
            int col = n0 + wn + nf * 8 + 2 * (lane & 3);
            *reinterpret_cast<float2*>(g_Y + (size_t)row * NCOL + col) =
                make_float2(acc[mf][nf][0], acc[mf][nf][1]);
            *reinterpret_cast<float2*>(g_Y + (size_t)(row + 8) * NCOL + col) =
                make_float2(acc[mf][nf][2], acc[mf][nf][3]);
        }
    }
}

// ---------------------------------------------------------------------------
// kernSteps: 32 fused sequential quantization steps.              [launch 4]
// ---------------------------------------------------------------------------
__global__ void kernSteps(const float* __restrict__ rn, const float* __restrict__ Wd) {
    int rloc = threadIdx.x >> 6, t = threadIdx.x & 63;
    int r = blockIdx.x * 4 + rloc;

    __shared__ float s_yh[4][64];
    __shared__ int s_nz[4];
    __shared__ unsigned char fl[4][32];

    float rnv = rn[r];
    if (t < 32) fl[rloc][t] = 0;

    for (int jb = NB - 1; jb >= 0; --jb) {
        __syncthreads();
        if (t == 0) s_nz[rloc] = 0;
        __syncthreads();

        float y = g_Y[(size_t)r * NCOL + jb * LAT + t];
        for (int jj = jb + 1; jj < NB; ++jj) {
            if (fl[rloc][jj]) {
                const float* wh = g_What + (size_t)r * NDIM + jj * BSZ;
                size_t go = (size_t)(jb * LAT + t) * NDIM + jj * BSZ;
#pragma unroll 4
                for (int k = 0; k < BSZ; ++k) {
                    float gv = __bfloat162float(g_Mt[0][go + k]) +
                               __bfloat162float(g_Mt[1][go + k]);
                    y -= wh[k] * gv;
                }
            }
        }
        y /= rnv;
        float yh = rintf(y);
        s_yh[rloc][t] = yh;
        if (yh != 0.f) s_nz[rloc] = 1;
        __syncthreads();

        int nz = s_nz[rloc];
        if (nz) {
            float x0 = 0.f, x1 = 0.f;
#pragma unroll 8
            for (int tt = 0; tt < 64; ++tt) {
                float v = s_yh[rloc][tt];
                x0 = fmaf(v, Wd[tt * BSZ + t], x0);
                x1 = fmaf(v, Wd[tt * BSZ + t + 64], x1);
            }
            float* dst = g_What + (size_t)r * NDIM + jb * BSZ;
            dst[t] = x0;
            dst[t + 64] = x1;
        }
        if (t == 0) {
            fl[rloc][jb] = (unsigned char)nz;
            g_flags[r * NB + jb] = (unsigned char)nz;
        }
    }
}

// ---------------------------------------------------------------------------
// kernOut: out = bias + x @ (W_hat * rn)^T, zero-block skipping.  [launch 5]
// ---------------------------------------------------------------------------
__global__ void kernOut(const float* __restrict__ x, const float* __restrict__ rn,
                        const float* __restrict__ bias, float* __restrict__ out) {
    __shared__ __align__(16) float xs[16][64];
    __shared__ __align__(16) float ws[16][64];
    __shared__ unsigned char shf[NB];

    int b0 = blockIdx.x * 64;
    int m0 = blockIdx.y * 64;
    int tid = threadIdx.x;

    if (tid < NB) {
        unsigned char f = 0;
        for (int mm = 0; mm < 64; ++mm) f |= g_flags[(m0 + mm) * NB + tid];
        shf[tid] = f;
    }
    __syncthreads();

    int tr = tid >> 4, tc = tid & 15;
    int l_r = tid >> 2, l_q = (tid & 3) * 4;

    float acc[4][4];
#pragma unroll
    for (int i = 0; i < 4; ++i)
#pragma unroll
        for (int q = 0; q < 4; ++q) acc[i][q] = 0.f;

    float rnm = rn[m0 + l_r];

    for (int jj = 0; jj < NB; ++jj) {
        if (!shf[jj]) continue;
        for (int k0 = 0; k0 < BSZ; k0 += 16) {
            float4 xv = *reinterpret_cast<const float4*>(x + (size_t)(b0 + l_r) * NDIM + jj * BSZ + k0 + l_q);
            xs[l_q + 0][l_r] = xv.x; xs[l_q + 1][l_r] = xv.y;
            xs[l_q + 2][l_r] = xv.z; xs[l_q + 3][l_r] = xv.w;
            float4 wv = *reinterpret_cast<const float4*>(g_What + (size_t)(m0 + l_r) * NDIM + jj * BSZ + k0 + l_q);
            ws[l_q + 0][l_r] = wv.x * rnm; ws[l_q + 1][l_r] = wv.y * rnm;
            ws[l_q + 2][l_r] = wv.z * rnm; ws[l_q + 3][l_r] = wv.w * rnm;
            __syncthreads();
#pragma unroll
            for (int kk = 0; kk < 16; ++kk) {
                float4 a4 = *reinterpret_cast<const float4*>(&xs[kk][tr * 4]);
                float4 b4 = *reinterpret_cast<const float4*>(&ws[kk][tc * 4]);
                float a[4] = {a4.x, a4.y, a4.z, a4.w};
                float b[4] = {b4.x, b4.y, b4.z, b4.w};
#pragma unroll
                for (int i = 0; i < 4; ++i)
#pragma unroll
                    for (int q = 0; q < 4; ++q)
                        acc[i][q] = fmaf(a[i], b[q], acc[i][q]);
            }
            __syncthreads();
        }
    }

#pragma unroll
    for (int i = 0; i < 4; ++i) {
        int b = b0 + tr * 4 + i;
#pragma unroll
        for (int q = 0; q < 4; ++q) {
            int m = m0 + tc * 4 + q;
            out[(size_t)b * NDIM + m] = bias[m] + acc[i][q];
        }
    }
}

// ---------------------------------------------------------------------------
// kernel_launch: inputs (metadata order): x, weight, bias, row_norm, L, We, Wd
// ---------------------------------------------------------------------------
extern "C" void kernel_launch(void* const* d_in, const int* in_sizes, int n_in,
                              void* d_out, int out_size) {
    (void)in_sizes; (void)n_in; (void)out_size;
    const float* x      = (const float*)d_in[0];
    const float* weight = (const float*)d_in[1];
    const float* bias   = (const float*)d_in[2];
    const float* rn     = (const float*)d_in[3];
    const float* L      = (const float*)d_in[4];
    const float* We     = (const float*)d_in[5];
    const float* Wd     = (const float*)d_in[6];
    float* out          = (float*)d_out;

    kernCvtW<<<8192, 256>>>(weight);                      // [0] W -> split bf16
    kernWeT<<<32, 256>>>(We);                             // [1] We^T split
    kernG<<<dim3(32, 32), 128, 30720>>>(L, We);           // [2] full Mt (G + diag + zeros)
    kernGemmY<<<dim3(32, 16), 256, 40960>>>();            // [3] Y = W @ M  <- profiled
    kernSteps<<<1024, 256>>>(rn, Wd);                     // [4] 32 fused steps
    kernOut<<<dim3(64, 64), 256>>>(x, rn, bias, out);     // [5] output GEMM
}